// round 1
// baseline (speedup 1.0000x reference)
#include <cuda_runtime.h>

// Problem constants
#define BB 16
#define LL 2048
#define HH 1024
#define ZZ 512

// Scratch (device globals; no allocation allowed)
__device__ float g_k[BB * HH];        // final @ Wk
__device__ float g_kq[BB * HH];       // Wq @ k
__device__ float g_w[BB * LL];        // logits, then softmax weights (in place)
__device__ float g_part[16 * BB * ZZ];// partial column sums of latent z
__device__ float g_S[BB * ZZ];        // (sum_i z[b,i]) @ Wv

// ---------------------------------------------------------------------------
// Kernel A: k[b,h] = sum_c final[b,c] * Wk[c,h]
// grid (8 hchunks, 16 b), 128 threads; Wk access coalesced across threads.
// ---------------------------------------------------------------------------
__global__ void kA_kproj(const float* __restrict__ fin, const float* __restrict__ Wk) {
    __shared__ float sF[HH];
    const int b = blockIdx.y;
    const int h = blockIdx.x * 128 + threadIdx.x;
    for (int j = threadIdx.x; j < HH; j += 128) sF[j] = fin[b * HH + j];
    __syncthreads();
    float acc = 0.f;
#pragma unroll 8
    for (int c = 0; c < HH; ++c) acc += sF[c] * Wk[(size_t)c * HH + h];
    g_k[b * HH + h] = acc;
}

// ---------------------------------------------------------------------------
// Kernel B: kq[b,r] = sum_c Wq[r,c] * k[b,c]   (warp per row, float4 reads)
// grid (32 rchunks, 16 b), 256 threads = 8 warps, 4 rows per warp.
// ---------------------------------------------------------------------------
__global__ void kB_kqproj(const float* __restrict__ Wq) {
    __shared__ __align__(16) float sk[HH];
    const int b = blockIdx.y;
    for (int j = threadIdx.x; j < HH; j += 256) sk[j] = g_k[b * HH + j];
    __syncthreads();
    const int warp = threadIdx.x >> 5, lane = threadIdx.x & 31;
    const float4* sk4 = (const float4*)sk;
#pragma unroll
    for (int j = 0; j < 4; ++j) {
        const int r = blockIdx.x * 32 + warp * 4 + j;
        const float4* wrow = (const float4*)(Wq + (size_t)r * HH);
        float acc = 0.f;
#pragma unroll
        for (int c = lane; c < HH / 4; c += 32) {
            float4 wv = wrow[c];
            float4 kv = sk4[c];
            acc += wv.x * kv.x + wv.y * kv.y + wv.z * kv.z + wv.w * kv.w;
        }
#pragma unroll
        for (int o = 16; o; o >>= 1) acc += __shfl_xor_sync(0xffffffffu, acc, o);
        if (lane == 0) g_kq[b * HH + r] = acc;
    }
}

// ---------------------------------------------------------------------------
// Kernel C: logit[b,i] = (enc[b,i] . kq[b]) / 32, masked to -1e9.
// grid 4096 blocks, 256 threads = 8 warps, one row per warp. Dominant read: enc.
// ---------------------------------------------------------------------------
__global__ void kC_logits(const float* __restrict__ enc, const int* __restrict__ mask) {
    const int warp = threadIdx.x >> 5, lane = threadIdx.x & 31;
    const int row = blockIdx.x * 8 + warp;          // 0 .. B*L-1
    const int b = row >> 11;
    const float4* e4 = (const float4*)(enc + (size_t)row * HH);
    const float4* kq4 = (const float4*)(g_kq + b * HH);
    float acc = 0.f;
#pragma unroll
    for (int c = lane; c < HH / 4; c += 32) {
        float4 ev = e4[c];
        float4 kv = __ldg(&kq4[c]);
        acc += ev.x * kv.x + ev.y * kv.y + ev.z * kv.z + ev.w * kv.w;
    }
#pragma unroll
    for (int o = 16; o; o >>= 1) acc += __shfl_xor_sync(0xffffffffu, acc, o);
    if (lane == 0) {
        float val = acc * 0.03125f;                 // / sqrt(1024)
        if (mask[row] == 0) val = -1e9f;
        g_w[row] = val;
    }
}

// ---------------------------------------------------------------------------
// Kernel D: per-batch softmax over L=2048 elements (in place in g_w).
// grid 16, 1024 threads (2 elements each).
// ---------------------------------------------------------------------------
__global__ void kD_softmax() {
    __shared__ float red[32];
    __shared__ float bc;
    const int b = blockIdx.x, t = threadIdx.x;
    const int warp = t >> 5, lane = t & 31;
    float x0 = g_w[b * LL + t];
    float x1 = g_w[b * LL + t + 1024];

    // block max
    float m = fmaxf(x0, x1);
#pragma unroll
    for (int o = 16; o; o >>= 1) m = fmaxf(m, __shfl_xor_sync(0xffffffffu, m, o));
    if (lane == 0) red[warp] = m;
    __syncthreads();
    if (warp == 0) {
        float v = red[lane];
#pragma unroll
        for (int o = 16; o; o >>= 1) v = fmaxf(v, __shfl_xor_sync(0xffffffffu, v, o));
        if (lane == 0) bc = v;
    }
    __syncthreads();
    const float M = bc;

    float e0 = (x0 <= -1e8f) ? 0.f : __expf(x0 - M);
    float e1 = (x1 <= -1e8f) ? 0.f : __expf(x1 - M);

    // block sum
    float s = e0 + e1;
#pragma unroll
    for (int o = 16; o; o >>= 1) s += __shfl_xor_sync(0xffffffffu, s, o);
    __syncthreads();
    if (lane == 0) red[warp] = s;
    __syncthreads();
    if (warp == 0) {
        float v = red[lane];
#pragma unroll
        for (int o = 16; o; o >>= 1) v += __shfl_xor_sync(0xffffffffu, v, o);
        if (lane == 0) bc = v;
    }
    __syncthreads();
    const float inv = 1.f / bc;

    g_w[b * LL + t] = e0 * inv;
    g_w[b * LL + t + 1024] = e1 * inv;
}

// ---------------------------------------------------------------------------
// Kernel E: partial column sums of latent z: g_part[chunk,b,z] = sum over 128 rows.
// grid (16 chunks, 16 b), 512 threads. Reads 67 MB coalesced.
// ---------------------------------------------------------------------------
__global__ void kE_zsum(const float* __restrict__ zin) {
    const int b = blockIdx.y, chunk = blockIdx.x, t = threadIdx.x;
    const float* base = zin + ((size_t)b * LL + (size_t)chunk * 128) * ZZ + t;
    float acc = 0.f;
#pragma unroll 8
    for (int i = 0; i < 128; ++i) acc += base[(size_t)i * ZZ];
    g_part[(chunk * BB + b) * ZZ + t] = acc;
}

// ---------------------------------------------------------------------------
// Kernel F: S[b,z] = sum_c zsum[b,c] * Wv[c,z]   (zsum = reduced partials)
// grid 16, 512 threads.
// ---------------------------------------------------------------------------
__global__ void kF_sproj(const float* __restrict__ Wv) {
    __shared__ float zs[ZZ];
    const int b = blockIdx.x, t = threadIdx.x;
    float acc = 0.f;
#pragma unroll
    for (int c = 0; c < 16; ++c) acc += g_part[(c * BB + b) * ZZ + t];
    zs[t] = acc;
    __syncthreads();
    float s = 0.f;
#pragma unroll 8
    for (int c = 0; c < ZZ; ++c) s += zs[c] * Wv[(size_t)c * ZZ + t];
    g_S[b * ZZ + t] = s;
}

// ---------------------------------------------------------------------------
// Kernel G: big fused writer.
//   output[b,i,z] = w[b,i] * S[b,z]   (first B*L*Z floats of d_out)
//   attn[b,i,j]   = w[b,i]            (next B*L*L floats)
// grid 32768 blocks (one per (b,i) row), 512 threads, float4 stores.
// ---------------------------------------------------------------------------
__global__ void kG_write(float* __restrict__ out) {
    const int row = blockIdx.x;            // 0 .. B*L-1
    const int b = row >> 11;
    const int t = threadIdx.x;
    const float wv = g_w[row];

    // attn row: 2048 floats = 512 float4
    float4* attn4 = (float4*)(out + (size_t)BB * LL * ZZ + (size_t)row * LL);
    attn4[t] = make_float4(wv, wv, wv, wv);

    // output row: 512 floats = 128 float4
    if (t < 128) {
        float4 sv = ((const float4*)(g_S + b * ZZ))[t];
        float4 ov = make_float4(wv * sv.x, wv * sv.y, wv * sv.z, wv * sv.w);
        ((float4*)(out + (size_t)row * ZZ))[t] = ov;
    }
}

// ---------------------------------------------------------------------------
extern "C" void kernel_launch(void* const* d_in, const int* in_sizes, int n_in,
                              void* d_out, int out_size) {
    const float* enc  = (const float*)d_in[0];  // [B,L,H]
    const float* fin  = (const float*)d_in[1];  // [B,H]
    const float* zseq = (const float*)d_in[2];  // [B,L,Z]
    const int*   mask = (const int*)  d_in[3];  // [B,L]
    const float* Wq   = (const float*)d_in[4];  // [H,H]
    const float* Wk   = (const float*)d_in[5];  // [H,H]
    const float* Wv   = (const float*)d_in[6];  // [Z,Z]
    float* out = (float*)d_out;

    kA_kproj<<<dim3(8, 16), 128>>>(fin, Wk);
    kB_kqproj<<<dim3(32, 16), 256>>>(Wq);
    kC_logits<<<4096, 256>>>(enc, mask);
    kD_softmax<<<16, 1024>>>();
    kE_zsum<<<dim3(16, 16), 512>>>(zseq);
    kF_sproj<<<16, 512>>>(Wv);
    kG_write<<<BB * LL, 512>>>(out);
}

// round 2
// speedup vs baseline: 1.8433x; 1.8433x over previous
#include <cuda_runtime.h>

#define BB 16
#define LL 2048
#define HH 1024
#define ZZ 512

// Scratch (device globals; no allocation allowed)
__device__ float g_k[BB * HH];         // final @ Wk
__device__ float g_kq[BB * HH];        // Wq @ k
__device__ float g_w[BB * LL];         // logits -> softmax weights (in place)
__device__ float g_part[16 * BB * ZZ]; // partial column sums of latent z
__device__ float g_S[BB * ZZ];         // (sum_i z[b,i]) @ Wv

// ---------------------------------------------------------------------------
// K1 (merged): blocks [0,128)  -> A: k[b,h] = fin[b,:] . Wk[:,h]
//              blocks [128,192)-> E: partial column sums of z (float4)
// 512 threads per block.
// ---------------------------------------------------------------------------
__global__ void __launch_bounds__(512) k1_prelim(
    const float* __restrict__ fin, const float* __restrict__ Wk,
    const float* __restrict__ zin)
{
    __shared__ __align__(16) float sh[HH];        // fin row (A)
    __shared__ float red[512];                     // c-slice reduce (A)
    const int blk = blockIdx.x;
    const int t = threadIdx.x;

    if (blk < 128) {
        // ---- A part: b = blk>>3, h-chunk = blk&7 (128 h), c split 4 ways ----
        const int b = blk >> 3;
        const int hof = t & 127;
        const int h = ((blk & 7) << 7) + hof;
        const int cs = t >> 7;                     // 0..3, each owns 256 c's
        for (int j = t; j < HH; j += 512) sh[j] = fin[b * HH + j];
        __syncthreads();
        float acc = 0.f;
        const float* wcol = Wk + h;
#pragma unroll 8
        for (int c = cs * 256; c < (cs + 1) * 256; ++c)
            acc += sh[c] * wcol[(size_t)c * HH];
        red[t] = acc;
        __syncthreads();
        if (cs == 0)
            g_k[b * HH + h] = red[hof] + red[128 + hof] + red[256 + hof] + red[384 + hof];
    } else {
        // ---- E part: 64 blocks, each = 4 chunks of 128 rows; thread owns a
        //      float4 column-group and sums 128 rows (coalesced, streaming) ----
        const int e = blk - 128;                   // 0..63
        const int b = e >> 2;
        const int chunk = (e & 3) * 4 + (t >> 7);  // 0..15
        const int col4 = t & 127;                  // float4 column
        const float4* base = (const float4*)zin
            + ((size_t)b * LL + (size_t)chunk * 128) * (ZZ / 4) + col4;
        float4 acc = make_float4(0.f, 0.f, 0.f, 0.f);
#pragma unroll 16
        for (int i = 0; i < 128; ++i) {
            float4 v = __ldcs(base + (size_t)i * (ZZ / 4));
            acc.x += v.x; acc.y += v.y; acc.z += v.z; acc.w += v.w;
        }
        ((float4*)g_part)[(chunk * BB + b) * (ZZ / 4) + col4] = acc;
    }
}

// ---------------------------------------------------------------------------
// K2 (merged): blocks [0,1024) -> B: kq[b,r] = Wq[r,:] . k[b,:]  (warp/row)
//              blocks [1024,1040) -> F: S[b,:] = (sum of partials) @ Wv
// 512 threads per block.
// ---------------------------------------------------------------------------
__global__ void __launch_bounds__(512) k2_proj(
    const float* __restrict__ Wq, const float* __restrict__ Wv)
{
    __shared__ __align__(16) float sh[HH];
    const int blk = blockIdx.x;
    const int t = threadIdx.x;

    if (blk < 1024) {
        // ---- B part ----
        const int b = blk >> 6;
        for (int j = t; j < HH; j += 512) sh[j] = g_k[b * HH + j];
        __syncthreads();
        const int warp = t >> 5, lane = t & 31;
        const int r = (blk & 63) * 16 + warp;
        const float4* wrow = (const float4*)(Wq + (size_t)r * HH);
        const float4* sk4 = (const float4*)sh;
        float acc = 0.f;
#pragma unroll
        for (int c = lane; c < HH / 4; c += 32) {
            float4 wv = wrow[c];
            float4 kv = sk4[c];
            acc += wv.x * kv.x + wv.y * kv.y + wv.z * kv.z + wv.w * kv.w;
        }
#pragma unroll
        for (int o = 16; o; o >>= 1) acc += __shfl_xor_sync(0xffffffffu, acc, o);
        if (lane == 0) g_kq[b * HH + r] = acc;
    } else {
        // ---- F part ----
        const int b = blk - 1024;
        float acc = 0.f;
#pragma unroll
        for (int c = 0; c < 16; ++c) acc += g_part[(c * BB + b) * ZZ + t];
        sh[t] = acc;
        __syncthreads();
        float s = 0.f;
#pragma unroll 8
        for (int c = 0; c < ZZ; ++c) s += sh[c] * Wv[(size_t)c * ZZ + t];
        g_S[b * ZZ + t] = s;
    }
}

// ---------------------------------------------------------------------------
// K3: logit[b,i] = (enc[b,i] . kq[b]) / 32, masked. Warp per row, streaming.
// ---------------------------------------------------------------------------
__global__ void __launch_bounds__(256) k3_logits(
    const float* __restrict__ enc, const int* __restrict__ mask)
{
    const int warp = threadIdx.x >> 5, lane = threadIdx.x & 31;
    const int row = blockIdx.x * 8 + warp;          // 0 .. B*L-1
    const int b = row >> 11;
    const float4* e4 = (const float4*)(enc + (size_t)row * HH);
    const float4* kq4 = (const float4*)(g_kq + b * HH);
    float acc = 0.f;
#pragma unroll
    for (int c = lane; c < HH / 4; c += 32) {
        float4 ev = __ldcs(&e4[c]);
        float4 kv = __ldg(&kq4[c]);
        acc += ev.x * kv.x + ev.y * kv.y + ev.z * kv.z + ev.w * kv.w;
    }
#pragma unroll
    for (int o = 16; o; o >>= 1) acc += __shfl_xor_sync(0xffffffffu, acc, o);
    if (lane == 0) {
        float val = acc * 0.03125f;                 // / sqrt(1024)
        if (mask[row] == 0) val = -1e9f;
        g_w[row] = val;
    }
}

// ---------------------------------------------------------------------------
// K4: per-batch softmax over L=2048 (in place). 16 blocks x 1024 threads.
// ---------------------------------------------------------------------------
__global__ void __launch_bounds__(1024) k4_softmax()
{
    __shared__ float red[32];
    __shared__ float bc;
    const int b = blockIdx.x, t = threadIdx.x;
    const int warp = t >> 5, lane = t & 31;
    float x0 = g_w[b * LL + t];
    float x1 = g_w[b * LL + t + 1024];

    float m = fmaxf(x0, x1);
#pragma unroll
    for (int o = 16; o; o >>= 1) m = fmaxf(m, __shfl_xor_sync(0xffffffffu, m, o));
    if (lane == 0) red[warp] = m;
    __syncthreads();
    if (warp == 0) {
        float v = red[lane];
#pragma unroll
        for (int o = 16; o; o >>= 1) v = fmaxf(v, __shfl_xor_sync(0xffffffffu, v, o));
        if (lane == 0) bc = v;
    }
    __syncthreads();
    const float M = bc;

    float e0 = (x0 <= -1e8f) ? 0.f : __expf(x0 - M);
    float e1 = (x1 <= -1e8f) ? 0.f : __expf(x1 - M);

    float s = e0 + e1;
#pragma unroll
    for (int o = 16; o; o >>= 1) s += __shfl_xor_sync(0xffffffffu, s, o);
    __syncthreads();
    if (lane == 0) red[warp] = s;
    __syncthreads();
    if (warp == 0) {
        float v = red[lane];
#pragma unroll
        for (int o = 16; o; o >>= 1) v += __shfl_xor_sync(0xffffffffu, v, o);
        if (lane == 0) bc = v;
    }
    __syncthreads();
    const float inv = 1.f / bc;

    g_w[b * LL + t] = e0 * inv;
    g_w[b * LL + t + 1024] = e1 * inv;
}

// ---------------------------------------------------------------------------
// K5: uniform streaming writer. One float4 store per thread.
//   gid <  ATTN4 : attn[b,i,j] = w[b,i]           (268 MB)
//   gid >= ATTN4 : output[b,i,z] = w[b,i]*S[b,z]  (67 MB)
// ---------------------------------------------------------------------------
__global__ void __launch_bounds__(256) k5_write(float* __restrict__ out)
{
    const long long ATTN4 = (long long)BB * LL * LL / 4;   // 16,777,216
    const long long gid = (long long)blockIdx.x * 256 + threadIdx.x;

    if (gid < ATTN4) {
        const int row = (int)(gid >> 9);                   // 512 float4 per attn row
        const float wv = g_w[row];                         // warp-uniform broadcast
        float4* p = (float4*)(out + (size_t)BB * LL * ZZ) + gid;
        __stcs(p, make_float4(wv, wv, wv, wv));
    } else {
        const long long g2 = gid - ATTN4;                  // < 4,194,304
        const int row = (int)(g2 >> 7);                    // 128 float4 per out row
        const int col = (int)(g2 & 127);
        const int b = row >> 11;
        const float wv = g_w[row];
        const float4 sv = __ldg(((const float4*)g_S) + b * 128 + col);
        __stcs((float4*)out + g2,
               make_float4(wv * sv.x, wv * sv.y, wv * sv.z, wv * sv.w));
    }
}

// ---------------------------------------------------------------------------
extern "C" void kernel_launch(void* const* d_in, const int* in_sizes, int n_in,
                              void* d_out, int out_size)
{
    const float* enc  = (const float*)d_in[0];  // [B,L,H]
    const float* fin  = (const float*)d_in[1];  // [B,H]
    const float* zseq = (const float*)d_in[2];  // [B,L,Z]
    const int*   mask = (const int*)  d_in[3];  // [B,L]
    const float* Wq   = (const float*)d_in[4];  // [H,H]
    const float* Wk   = (const float*)d_in[5];  // [H,H]
    const float* Wv   = (const float*)d_in[6];  // [Z,Z]
    float* out = (float*)d_out;

    k1_prelim<<<192, 512>>>(fin, Wk, zseq);
    k2_proj<<<1040, 512>>>(Wq, Wv);
    k3_logits<<<4096, 256>>>(enc, mask);
    k4_softmax<<<16, 1024>>>();
    // attn float4 (16,777,216) + out float4 (4,194,304) = 20,971,520 / 256
    k5_write<<<81920, 256>>>(out);
}

// round 3
// speedup vs baseline: 1.8769x; 1.0182x over previous
#include <cuda_runtime.h>

#define BB 16
#define LL 2048
#define HH 1024
#define ZZ 512

// Scratch (device globals; no allocation allowed)
__device__ float g_k[BB * HH];         // final @ Wk
__device__ float g_kq[BB * HH];        // Wq @ k
__device__ float g_w[BB * LL];         // RAW masked logits (softmax folded into k5)
__device__ float g_part[16 * BB * ZZ]; // partial column sums of latent z
__device__ float g_S[BB * ZZ];         // (sum_i z[b,i]) @ Wv

// ---------------------------------------------------------------------------
// K1 (merged): blocks [0,128)  -> A: k[b,h] = fin[b,:] . Wk[:,h]
//              blocks [128,192)-> E: partial column sums of z (float4, streaming)
// ---------------------------------------------------------------------------
__global__ void __launch_bounds__(512) k1_prelim(
    const float* __restrict__ fin, const float* __restrict__ Wk,
    const float* __restrict__ zin)
{
    __shared__ __align__(16) float sh[HH];
    __shared__ float red[512];
    const int blk = blockIdx.x;
    const int t = threadIdx.x;

    if (blk < 128) {
        const int b = blk >> 3;
        const int hof = t & 127;
        const int h = ((blk & 7) << 7) + hof;
        const int cs = t >> 7;
        for (int j = t; j < HH; j += 512) sh[j] = fin[b * HH + j];
        __syncthreads();
        float acc = 0.f;
        const float* wcol = Wk + h;
#pragma unroll 8
        for (int c = cs * 256; c < (cs + 1) * 256; ++c)
            acc += sh[c] * wcol[(size_t)c * HH];
        red[t] = acc;
        __syncthreads();
        if (cs == 0)
            g_k[b * HH + h] = red[hof] + red[128 + hof] + red[256 + hof] + red[384 + hof];
    } else {
        const int e = blk - 128;
        const int b = e >> 2;
        const int chunk = (e & 3) * 4 + (t >> 7);
        const int col4 = t & 127;
        const float4* base = (const float4*)zin
            + ((size_t)b * LL + (size_t)chunk * 128) * (ZZ / 4) + col4;
        float4 acc = make_float4(0.f, 0.f, 0.f, 0.f);
#pragma unroll 16
        for (int i = 0; i < 128; ++i) {
            float4 v = __ldcs(base + (size_t)i * (ZZ / 4));
            acc.x += v.x; acc.y += v.y; acc.z += v.z; acc.w += v.w;
        }
        ((float4*)g_part)[(chunk * BB + b) * (ZZ / 4) + col4] = acc;
    }
}

// ---------------------------------------------------------------------------
// K2 (merged): blocks [0,1024) -> B: kq[b,r] = Wq[r,:] . k[b,:]
//              blocks [1024,1040) -> F: S[b,:] = (sum of partials) @ Wv
// ---------------------------------------------------------------------------
__global__ void __launch_bounds__(512) k2_proj(
    const float* __restrict__ Wq, const float* __restrict__ Wv)
{
    __shared__ __align__(16) float sh[HH];
    const int blk = blockIdx.x;
    const int t = threadIdx.x;

    if (blk < 1024) {
        const int b = blk >> 6;
        for (int j = t; j < HH; j += 512) sh[j] = g_k[b * HH + j];
        __syncthreads();
        const int warp = t >> 5, lane = t & 31;
        const int r = (blk & 63) * 16 + warp;
        const float4* wrow = (const float4*)(Wq + (size_t)r * HH);
        const float4* sk4 = (const float4*)sh;
        float acc = 0.f;
#pragma unroll
        for (int c = lane; c < HH / 4; c += 32) {
            float4 wv = wrow[c];
            float4 kv = sk4[c];
            acc += wv.x * kv.x + wv.y * kv.y + wv.z * kv.z + wv.w * kv.w;
        }
#pragma unroll
        for (int o = 16; o; o >>= 1) acc += __shfl_xor_sync(0xffffffffu, acc, o);
        if (lane == 0) g_kq[b * HH + r] = acc;
    } else {
        const int b = blk - 1024;
        float acc = 0.f;
#pragma unroll
        for (int c = 0; c < 16; ++c) acc += g_part[(c * BB + b) * ZZ + t];
        sh[t] = acc;
        __syncthreads();
        float s = 0.f;
#pragma unroll 8
        for (int c = 0; c < ZZ; ++c) s += sh[c] * Wv[(size_t)c * ZZ + t];
        g_S[b * ZZ + t] = s;
    }
}

// ---------------------------------------------------------------------------
// K3: raw masked logit[b,i] = (enc[b,i] . kq[b]) / 32, or -1e9. Warp per row.
// ---------------------------------------------------------------------------
__global__ void __launch_bounds__(256) k3_logits(
    const float* __restrict__ enc, const int* __restrict__ mask)
{
    const int warp = threadIdx.x >> 5, lane = threadIdx.x & 31;
    const int row = blockIdx.x * 8 + warp;
    const int b = row >> 11;
    const float4* e4 = (const float4*)(enc + (size_t)row * HH);
    const float4* kq4 = (const float4*)(g_kq + b * HH);
    float acc = 0.f;
#pragma unroll
    for (int c = lane; c < HH / 4; c += 32) {
        float4 ev = __ldcs(&e4[c]);
        float4 kv = __ldg(&kq4[c]);
        acc += ev.x * kv.x + ev.y * kv.y + ev.z * kv.z + ev.w * kv.w;
    }
#pragma unroll
    for (int o = 16; o; o >>= 1) acc += __shfl_xor_sync(0xffffffffu, acc, o);
    if (lane == 0) {
        float val = acc * 0.03125f;
        if (mask[row] == 0) val = -1e9f;
        g_w[row] = val;
    }
}

// ---------------------------------------------------------------------------
// K5: fused softmax + streaming writer. 10240 blocks x 256 threads,
// 2048 float4 per block (8 per thread).
//   blocks [0,8192)     : attn region, 512 blocks per batch
//   blocks [8192,10240) : out region,  128 blocks per batch
// Preamble per block: softmax stats (max, inv-sum) of its batch from L2.
// ---------------------------------------------------------------------------
__global__ void __launch_bounds__(256) k5_write(float* __restrict__ out)
{
    __shared__ float red[8];
    __shared__ float s_max, s_inv;
    const int blk = blockIdx.x;
    const int t = threadIdx.x;
    const int warp = t >> 5, lane = t & 31;

    const bool is_attn = (blk < 8192);
    const int b = is_attn ? (blk >> 9) : ((blk - 8192) >> 7);

    // ---- per-block softmax stats over this batch's 2048 logits ----
    float lg[8];
#pragma unroll
    for (int k = 0; k < 8; ++k) lg[k] = __ldg(&g_w[b * LL + k * 256 + t]);

    float m = lg[0];
#pragma unroll
    for (int k = 1; k < 8; ++k) m = fmaxf(m, lg[k]);
#pragma unroll
    for (int o = 16; o; o >>= 1) m = fmaxf(m, __shfl_xor_sync(0xffffffffu, m, o));
    if (lane == 0) red[warp] = m;
    __syncthreads();
    if (warp == 0 && lane < 8) {
        float v = red[lane];
#pragma unroll
        for (int o = 4; o; o >>= 1) v = fmaxf(v, __shfl_xor_sync(0xffu, v, o));
        if (lane == 0) s_max = v;
    }
    __syncthreads();
    const float M = s_max;

    float s = 0.f;
#pragma unroll
    for (int k = 0; k < 8; ++k) s += __expf(lg[k] - M);   // -1e9 rows underflow to 0
#pragma unroll
    for (int o = 16; o; o >>= 1) s += __shfl_xor_sync(0xffffffffu, s, o);
    __syncthreads();
    if (lane == 0) red[warp] = s;
    __syncthreads();
    if (warp == 0 && lane < 8) {
        float v = red[lane];
#pragma unroll
        for (int o = 4; o; o >>= 1) v += __shfl_xor_sync(0xffu, v, o);
        if (lane == 0) s_inv = 1.f / v;
    }
    __syncthreads();
    const float inv = s_inv;

    // ---- 8 streaming float4 stores per thread ----
    if (is_attn) {
        // per-batch attn region: 1,048,576 float4; this block's tile: 2048
        const long long base = (long long)b * (LL * LL / 4)
                             + (long long)(blk & 511) * 2048;
        float4* attn4 = (float4*)(out + (size_t)BB * LL * ZZ);
#pragma unroll
        for (int k = 0; k < 8; ++k) {
            const long long idx = base + k * 256 + t;
            const int row = (int)(idx >> 9);               // 512 float4 per row
            const float wv = __expf(__ldg(&g_w[row]) - M) * inv;
            __stcs(attn4 + idx, make_float4(wv, wv, wv, wv));
        }
    } else {
        const int e = blk - 8192;
        const long long base = (long long)b * (LL * ZZ / 4)
                             + (long long)(e & 127) * 2048;
        const float4* S4 = (const float4*)g_S + b * (ZZ / 4);
#pragma unroll
        for (int k = 0; k < 8; ++k) {
            const long long idx = base + k * 256 + t;
            const int row = (int)(idx >> 7);               // 128 float4 per row
            const int col = (int)(idx & 127);
            const float wv = __expf(__ldg(&g_w[row]) - M) * inv;
            const float4 sv = __ldg(&S4[col]);
            __stcs((float4*)out + idx,
                   make_float4(wv * sv.x, wv * sv.y, wv * sv.z, wv * sv.w));
        }
    }
}

// ---------------------------------------------------------------------------
extern "C" void kernel_launch(void* const* d_in, const int* in_sizes, int n_in,
                              void* d_out, int out_size)
{
    const float* enc  = (const float*)d_in[0];
    const float* fin  = (const float*)d_in[1];
    const float* zseq = (const float*)d_in[2];
    const int*   mask = (const int*)  d_in[3];
    const float* Wq   = (const float*)d_in[4];
    const float* Wk   = (const float*)d_in[5];
    const float* Wv   = (const float*)d_in[6];
    float* out = (float*)d_out;

    k1_prelim<<<192, 512>>>(fin, Wk, zseq);
    k2_proj<<<1040, 512>>>(Wq, Wv);
    k3_logits<<<4096, 256>>>(enc, mask);
    k5_write<<<10240, 256>>>(out);
}

// round 4
// speedup vs baseline: 1.9750x; 1.0523x over previous
#include <cuda_runtime.h>

#define BB 16
#define LL 2048
#define HH 1024
#define ZZ 512

// Scratch (device globals; no allocation allowed)
__device__ float g_k[BB * HH];         // final @ Wk
__device__ float g_kq[BB * HH];        // Wq @ k
__device__ float g_w[BB * LL];         // RAW masked logits (softmax folded into k5)
__device__ float g_part[32 * BB * ZZ]; // partial column sums of latent z (32 chunks)
__device__ float g_S[BB * ZZ];         // (sum_i z[b,i]) @ Wv

// ---------------------------------------------------------------------------
// K1 (merged): blocks [0,128)   -> A: k[b,h] = fin[b,:] . Wk[:,h]
//              blocks [128,640) -> E: partial column sums of z
//                                  one block per (b, 64-row chunk); thread =
//                                  one scalar column (coalesced 2KB/row).
// ---------------------------------------------------------------------------
__global__ void __launch_bounds__(512) k1_prelim(
    const float* __restrict__ fin, const float* __restrict__ Wk,
    const float* __restrict__ zin)
{
    __shared__ __align__(16) float sh[HH];
    __shared__ float red[512];
    const int blk = blockIdx.x;
    const int t = threadIdx.x;

    if (blk < 128) {
        // ---- A part ----
        const int b = blk >> 3;
        const int hof = t & 127;
        const int h = ((blk & 7) << 7) + hof;
        const int cs = t >> 7;
        for (int j = t; j < HH; j += 512) sh[j] = fin[b * HH + j];
        __syncthreads();
        float acc = 0.f;
        const float* wcol = Wk + h;
#pragma unroll 8
        for (int c = cs * 256; c < (cs + 1) * 256; ++c)
            acc += sh[c] * wcol[(size_t)c * HH];
        red[t] = acc;
        __syncthreads();
        if (cs == 0)
            g_k[b * HH + h] = red[hof] + red[128 + hof] + red[256 + hof] + red[384 + hof];
    } else {
        // ---- E part: 512 blocks ----
        const int e = blk - 128;                 // 0..511
        const int b = e >> 5;                    // batch
        const int chunk = e & 31;                // 64-row chunk
        const float* base = zin + ((size_t)b * LL + (size_t)chunk * 64) * ZZ + t;
        float acc = 0.f;
#pragma unroll 16
        for (int i = 0; i < 64; ++i) acc += __ldcs(base + (size_t)i * ZZ);
        g_part[(chunk * BB + b) * ZZ + t] = acc;
    }
}

// ---------------------------------------------------------------------------
// K2 (merged): blocks [0,1024) -> B: kq[b,r] = Wq[r,:] . k[b,:]
//              blocks [1024,1040) -> F: S[b,:] = (sum of 32 partials) @ Wv
// ---------------------------------------------------------------------------
__global__ void __launch_bounds__(512) k2_proj(
    const float* __restrict__ Wq, const float* __restrict__ Wv)
{
    __shared__ __align__(16) float sh[HH];
    const int blk = blockIdx.x;
    const int t = threadIdx.x;

    if (blk < 1024) {
        const int b = blk >> 6;
        for (int j = t; j < HH; j += 512) sh[j] = g_k[b * HH + j];
        __syncthreads();
        const int warp = t >> 5, lane = t & 31;
        const int r = (blk & 63) * 16 + warp;
        const float4* wrow = (const float4*)(Wq + (size_t)r * HH);
        const float4* sk4 = (const float4*)sh;
        float acc = 0.f;
#pragma unroll
        for (int c = lane; c < HH / 4; c += 32) {
            float4 wv = wrow[c];
            float4 kv = sk4[c];
            acc += wv.x * kv.x + wv.y * kv.y + wv.z * kv.z + wv.w * kv.w;
        }
#pragma unroll
        for (int o = 16; o; o >>= 1) acc += __shfl_xor_sync(0xffffffffu, acc, o);
        if (lane == 0) g_kq[b * HH + r] = acc;
    } else {
        const int b = blk - 1024;
        float acc = 0.f;
#pragma unroll
        for (int c = 0; c < 32; ++c) acc += g_part[(c * BB + b) * ZZ + t];
        sh[t] = acc;
        __syncthreads();
        float s = 0.f;
#pragma unroll 8
        for (int c = 0; c < ZZ; ++c) s += sh[c] * Wv[(size_t)c * ZZ + t];
        g_S[b * ZZ + t] = s;
    }
}

// ---------------------------------------------------------------------------
// K3: raw masked logit[b,i] = (enc[b,i] . kq[b]) / 32, or -1e9. Warp per row.
// ---------------------------------------------------------------------------
__global__ void __launch_bounds__(256) k3_logits(
    const float* __restrict__ enc, const int* __restrict__ mask)
{
    const int warp = threadIdx.x >> 5, lane = threadIdx.x & 31;
    const int row = blockIdx.x * 8 + warp;
    const int b = row >> 11;
    const float4* e4 = (const float4*)(enc + (size_t)row * HH);
    const float4* kq4 = (const float4*)(g_kq + b * HH);
    float acc = 0.f;
#pragma unroll
    for (int c = lane; c < HH / 4; c += 32) {
        float4 ev = __ldcs(&e4[c]);
        float4 kv = __ldg(&kq4[c]);
        acc += ev.x * kv.x + ev.y * kv.y + ev.z * kv.z + ev.w * kv.w;
    }
#pragma unroll
    for (int o = 16; o; o >>= 1) acc += __shfl_xor_sync(0xffffffffu, acc, o);
    if (lane == 0) {
        float val = acc * 0.03125f;
        if (mask[row] == 0) val = -1e9f;
        g_w[row] = val;
    }
}

// ---------------------------------------------------------------------------
// K5: fused softmax + streaming writer. 5120 blocks x 256 threads,
// 4096 float4 per block (16 per thread).
//   blocks [0,4096)    : attn region, 256 blocks per batch
//   blocks [4096,5120) : out region,   64 blocks per batch
// ---------------------------------------------------------------------------
__global__ void __launch_bounds__(256) k5_write(float* __restrict__ out)
{
    __shared__ float red[8];
    __shared__ float s_max, s_inv;
    const int blk = blockIdx.x;
    const int t = threadIdx.x;
    const int warp = t >> 5, lane = t & 31;

    const bool is_attn = (blk < 4096);
    const int b = is_attn ? (blk >> 8) : ((blk - 4096) >> 6);

    // ---- per-block softmax stats over this batch's 2048 logits ----
    float lg[8];
#pragma unroll
    for (int k = 0; k < 8; ++k) lg[k] = __ldg(&g_w[b * LL + k * 256 + t]);

    float m = lg[0];
#pragma unroll
    for (int k = 1; k < 8; ++k) m = fmaxf(m, lg[k]);
#pragma unroll
    for (int o = 16; o; o >>= 1) m = fmaxf(m, __shfl_xor_sync(0xffffffffu, m, o));
    if (lane == 0) red[warp] = m;
    __syncthreads();
    if (warp == 0 && lane < 8) {
        float v = red[lane];
#pragma unroll
        for (int o = 4; o; o >>= 1) v = fmaxf(v, __shfl_xor_sync(0xffu, v, o));
        if (lane == 0) s_max = v;
    }
    __syncthreads();
    const float M = s_max;

    float s = 0.f;
#pragma unroll
    for (int k = 0; k < 8; ++k) s += __expf(lg[k] - M);   // -1e9 rows underflow to 0
#pragma unroll
    for (int o = 16; o; o >>= 1) s += __shfl_xor_sync(0xffffffffu, s, o);
    __syncthreads();
    if (lane == 0) red[warp] = s;
    __syncthreads();
    if (warp == 0 && lane < 8) {
        float v = red[lane];
#pragma unroll
        for (int o = 4; o; o >>= 1) v += __shfl_xor_sync(0xffu, v, o);
        if (lane == 0) s_inv = 1.f / v;
    }
    __syncthreads();
    const float inv = s_inv;

    // ---- 16 streaming float4 stores per thread ----
    if (is_attn) {
        const long long base = (long long)b * (LL * LL / 4)
                             + (long long)(blk & 255) * 4096;
        float4* attn4 = (float4*)(out + (size_t)BB * LL * ZZ);
#pragma unroll
        for (int k = 0; k < 16; ++k) {
            const long long idx = base + k * 256 + t;
            const int row = (int)(idx >> 9);               // 512 float4 per row
            const float wv = __expf(__ldg(&g_w[row]) - M) * inv;
            __stcs(attn4 + idx, make_float4(wv, wv, wv, wv));
        }
    } else {
        const int e = blk - 4096;
        const long long base = (long long)b * (LL * ZZ / 4)
                             + (long long)(e & 63) * 4096;
        const float4* S4 = (const float4*)g_S + b * (ZZ / 4);
#pragma unroll
        for (int k = 0; k < 16; ++k) {
            const long long idx = base + k * 256 + t;
            const int row = (int)(idx >> 7);               // 128 float4 per row
            const int col = (int)(idx & 127);
            const float wv = __expf(__ldg(&g_w[row]) - M) * inv;
            const float4 sv = __ldg(&S4[col]);
            __stcs((float4*)out + idx,
                   make_float4(wv * sv.x, wv * sv.y, wv * sv.z, wv * sv.w));
        }
    }
}

// ---------------------------------------------------------------------------
extern "C" void kernel_launch(void* const* d_in, const int* in_sizes, int n_in,
                              void* d_out, int out_size)
{
    const float* enc  = (const float*)d_in[0];
    const float* fin  = (const float*)d_in[1];
    const float* zseq = (const float*)d_in[2];
    const int*   mask = (const int*)  d_in[3];
    const float* Wq   = (const float*)d_in[4];
    const float* Wk   = (const float*)d_in[5];
    const float* Wv   = (const float*)d_in[6];
    float* out = (float*)d_out;

    k1_prelim<<<640, 512>>>(fin, Wk, zseq);
    k2_proj<<<1040, 512>>>(Wq, Wv);
    k3_logits<<<4096, 256>>>(enc, mask);
    k5_write<<<5120, 256>>>(out);
}